// round 14
// baseline (speedup 1.0000x reference)
#include <cuda_runtime.h>
#include <cuda_bf16.h>
#include <mma.h>
#include <math.h>

using namespace nvcuda;

#define Nn 50000
#define NR 50048
#define Ee 800000
#define Dd 32
#define NL 6
#define KK 160
#define CN 96
#define BM 128
#define A_LD 40
#define B_LD 104
#define GEMM_SMEM ((2*KK*B_LD + 4*BM*A_LD) * 2)   // 107520 bytes

// ---------------- device scratch ----------------
// g_deg/g_indeg/g_sum/g_tot are zero on first use and re-zeroed in k_final.
__device__ float g_h0[Nn * Dd];
__device__ float g_h1[Nn * Dd];
__device__ __nv_bfloat16 g_Xh[NR * KK];
__device__ __nv_bfloat16 g_Xl[NR * KK];
__device__ __nv_bfloat16 g_Wbh[NL * KK * CN];
__device__ __nv_bfloat16 g_Wbl[NL * KK * CN];
__device__ float g_scale[Nn];
__device__ float g_deg[Nn];
__device__ int   g_indeg[Nn];
__device__ int   g_start[Nn];
__device__ int   g_cursor[Nn];
__device__ int2  g_csr[Ee + 8];     // +8 pad: 4-wide uniform reads may overrun a segment tail
__device__ float g_rel[NL * Dd];
__device__ float g_D[Nn];
__device__ float g_sum;
__device__ int   g_tot;
__device__ int   g_pred[Nn];

__device__ __forceinline__ float* hbuf(int s) { return s ? g_h1 : g_h0; }

// ------- init + edge count fused ------
__global__ void k_init(const int* __restrict__ hptr, const float* __restrict__ q,
                       const float* __restrict__ relW, const float* __restrict__ relb,
                       const float* __restrict__ linW,
                       const int* __restrict__ node_out, const float* __restrict__ ew) {
    int idx = blockIdx.x * blockDim.x + threadIdx.x;
    if (idx < Nn * Dd) {
        int n = idx >> 5;
        int h = *hptr;
        g_h0[idx] = (n == h) ? 0.0f : 100.0f;
    }
    if (idx < NL * KK * CN) {
        int l = idx / (KK * CN);
        int rem = idx % (KK * CN);
        int k = rem / CN;
        int j = rem % CN;
        float v;
        if (k < 32) {
            v = (j < 32) ? linW[(l * 416 + k) * 32 + j] : 0.0f;
        } else {
            int f = k - 32, g = j >> 5, d = j & 31;
            v = linW[(l * 416 + 32 + f * 3 + g) * 32 + d];
        }
        __nv_bfloat16 hh = __float2bfloat16_rn(v);
        g_Wbh[idx] = hh;
        g_Wbl[idx] = __float2bfloat16_rn(v - __bfloat162float(hh));
    }
    if (idx < NL * Dd) {
        int i = idx >> 5, d = idx & 31;
        float acc = relb[i * Dd + d];
        for (int k = 0; k < Dd; k++)
            acc += q[k] * relW[(i * Dd + k) * Dd + d];
        g_rel[i * Dd + d] = acc;
    }
    if (idx < 8) g_csr[Ee + idx] = make_int2(0, 0);
    if (idx < Ee) {
        int o = node_out[idx];
        atomicAdd(&g_deg[o], ew[idx]);
        atomicAdd(&g_indeg[o], 1);
    }
}

// ---------------- segment allocation + log(deg) partial sum ----------------
__global__ void k_alloc() {
    int i = blockIdx.x * blockDim.x + threadIdx.x;
    float s = 0.0f;
    if (i < Nn) {
        int c = g_indeg[i];
        int st = atomicAdd(&g_tot, c);
        g_start[i] = st;
        g_cursor[i] = st;
        s = logf(g_deg[i] + 1.0f);
        g_scale[i] = s;
    }
    for (int o = 16; o; o >>= 1) s += __shfl_xor_sync(0xffffffffu, s, o);
    __shared__ float wsum[8];
    int lane = threadIdx.x & 31, wid = threadIdx.x >> 5;
    if (lane == 0) wsum[wid] = s;
    __syncthreads();
    if (threadIdx.x == 0) {
        float t = 0.0f;
        for (int w = 0; w < 8; w++) t += wsum[w];
        atomicAdd(&g_sum, t);
    }
}

// ---------------- CSR scatter + scale normalize ----------------
__global__ void k_scatter(const int* __restrict__ node_out, const int* __restrict__ node_in,
                          const float* __restrict__ ew) {
    int e = blockIdx.x * blockDim.x + threadIdx.x;
    if (e < Nn) g_scale[e] = g_scale[e] * ((float)Nn / g_sum);
    if (e >= Ee) return;
    int n = node_out[e];
    int p = atomicAdd(&g_cursor[n], 1);
    g_csr[p] = make_int2(node_in[e], __float_as_int(ew[e]));
}

// ---------------- aggregation: warp per node, lane = dim, MLP=4,
// uniform (broadcast) CSR loads — no shfl staging ----------------
template <int LAST>
__global__ void __launch_bounds__(256, 8)
k_agg(const int* __restrict__ hptr, int insel, int layer) {
    int warp = (blockIdx.x * blockDim.x + threadIdx.x) >> 5;
    int lane = threadIdx.x & 31;
    if (warp >= Nn) return;
    int n = warp;
    const float* __restrict__ hin = hbuf(insel);
    int h = *hptr;
    float relv = g_rel[layer * Dd + lane];
    const float INF = __int_as_float(0x7f800000);

    float b = (n == h) ? 0.0f : 100.0f;
    float sumv = 0.0f, sqv = 0.0f, mxv = -INF, mnv = INF;
    float bestS = 32.0f * b;
    int bestSrc = n;

    int cnt = g_indeg[n];
    const int2* __restrict__ cs = g_csr + g_start[n];

    int j = 0;
    for (; j + 4 <= cnt; j += 4) {
        // uniform loads: all lanes read the same address -> 1 broadcast wavefront
        int2 e0 = cs[j + 0];
        int2 e1 = cs[j + 1];
        int2 e2 = cs[j + 2];
        int2 e3 = cs[j + 3];
        float w0 = __int_as_float(e0.y);
        float w1 = __int_as_float(e1.y);
        float w2 = __int_as_float(e2.y);
        float w3 = __int_as_float(e3.y);
        // issue all gathers before accumulating (MLP=4)
        float v0 = hin[e0.x * Dd + lane];
        float v1 = hin[e1.x * Dd + lane];
        float v2 = hin[e2.x * Dd + lane];
        float v3 = hin[e3.x * Dd + lane];
        float D0 = 0.f, D1 = 0.f, D2 = 0.f, D3 = 0.f;
        if (LAST) { D0 = g_D[e0.x]; D1 = g_D[e1.x]; D2 = g_D[e2.x]; D3 = g_D[e3.x]; }

        float wv0 = v0 * w0;
        sumv += wv0; sqv += v0 * wv0;
        mxv = fmaxf(mxv, wv0); mnv = fminf(mnv, wv0);
        float wv1 = v1 * w1;
        sumv += wv1; sqv += v1 * wv1;
        mxv = fmaxf(mxv, wv1); mnv = fminf(mnv, wv1);
        float wv2 = v2 * w2;
        sumv += wv2; sqv += v2 * wv2;
        mxv = fmaxf(mxv, wv2); mnv = fminf(mnv, wv2);
        float wv3 = v3 * w3;
        sumv += wv3; sqv += v3 * wv3;
        mxv = fmaxf(mxv, wv3); mnv = fminf(mnv, wv3);

        if (LAST) {
            float sc0 = w0 * D0, sc1 = w1 * D1, sc2 = w2 * D2, sc3 = w3 * D3;
            if (sc0 > bestS) { bestS = sc0; bestSrc = e0.x; }
            else if (sc0 == bestS) bestSrc = min(bestSrc, e0.x);
            if (sc1 > bestS) { bestS = sc1; bestSrc = e1.x; }
            else if (sc1 == bestS) bestSrc = min(bestSrc, e1.x);
            if (sc2 > bestS) { bestS = sc2; bestSrc = e2.x; }
            else if (sc2 == bestS) bestSrc = min(bestSrc, e2.x);
            if (sc3 > bestS) { bestS = sc3; bestSrc = e3.x; }
            else if (sc3 == bestS) bestSrc = min(bestSrc, e3.x);
        }
    }
    for (; j < cnt; j++) {
        int2 e0 = cs[j];
        float w0 = __int_as_float(e0.y);
        float v0 = hin[e0.x * Dd + lane];
        float wv0 = v0 * w0;
        sumv += wv0; sqv += v0 * wv0;
        mxv = fmaxf(mxv, wv0); mnv = fminf(mnv, wv0);
        if (LAST) {
            float sc = w0 * g_D[e0.x];
            if (sc > bestS) { bestS = sc; bestSrc = e0.x; }
            else if (sc == bestS) bestSrc = min(bestSrc, e0.x);
        }
    }

    float sum = relv * sumv + b;
    float sq = relv * relv * sqv + b * b;
    float mx, mn;
    if (cnt > 0) {
        float emax = (relv >= 0.0f) ? relv * mxv : relv * mnv;
        float emin = (relv >= 0.0f) ? relv * mnv : relv * mxv;
        mx = fmaxf(emax, b);
        mn = fminf(emin, b);
    } else {
        mx = b; mn = b;
    }

    float c = (float)(cnt + 1);
    float mean = sum / c;
    float sqm = sq / c;
    float sd = sqrtf(fmaxf(sqm - mean * mean, 1e-6f));

    float hv = hin[n * Dd + lane];
    __nv_bfloat16 hh = __float2bfloat16_rn(hv);
    g_Xh[n * KK + lane] = hh;
    g_Xl[n * KK + lane] = __float2bfloat16_rn(hv - __bfloat162float(hh));

    union { __nv_bfloat16 v[4]; uint2 u; } ph, pl;
    float fv[4] = {mean, mx, mn, sd};
    #pragma unroll
    for (int t = 0; t < 4; t++) {
        __nv_bfloat16 fh = __float2bfloat16_rn(fv[t]);
        ph.v[t] = fh;
        pl.v[t] = __float2bfloat16_rn(fv[t] - __bfloat162float(fh));
    }
    *reinterpret_cast<uint2*>(&g_Xh[n * KK + Dd + lane * 4]) = ph.u;
    *reinterpret_cast<uint2*>(&g_Xl[n * KK + Dd + lane * 4]) = pl.u;

    if (LAST && lane == 0) g_pred[n] = bestSrc;
}

// ---------------- tensor-core GEMM (R10 winner: BM=128, 2x3 warp tile) --------
template <int DOT>
__global__ void k_gemm(const float* __restrict__ linb, int layer, int outsel) {
    extern __shared__ char sm_[];
    __nv_bfloat16* Bh = reinterpret_cast<__nv_bfloat16*>(sm_);
    __nv_bfloat16* Bl = Bh + KK * B_LD;
    __nv_bfloat16* Ah = Bl + KK * B_LD;
    __nv_bfloat16* Al = Ah + 2 * BM * A_LD;
    float* Cs = reinterpret_cast<float*>(sm_);

    float* __restrict__ hout = hbuf(outsel);
    int row0 = blockIdx.x * BM;
    int wid = threadIdx.x >> 5;
    int lane = threadIdx.x & 31;
    int wm = wid >> 1;
    int wn = wid & 1;

    {
        const uint4* srcH = reinterpret_cast<const uint4*>(g_Wbh + layer * KK * CN);
        const uint4* srcL = reinterpret_cast<const uint4*>(g_Wbl + layer * KK * CN);
        for (int i = threadIdx.x; i < KK * CN / 8; i += 256) {
            int r = i / 12, c = i % 12;
            reinterpret_cast<uint4*>(Bh + r * B_LD)[c] = srcH[i];
            reinterpret_cast<uint4*>(Bl + r * B_LD)[c] = srcL[i];
        }
    }
    {
        for (int i = threadIdx.x; i < BM * 4; i += 256) {
            int r = i >> 2, c = i & 3;
            size_t goff = (size_t)(row0 + r) * KK + c * 8;
            reinterpret_cast<uint4*>(Ah + r * A_LD)[c] =
                *reinterpret_cast<const uint4*>(g_Xh + goff);
            reinterpret_cast<uint4*>(Al + r * A_LD)[c] =
                *reinterpret_cast<const uint4*>(g_Xl + goff);
        }
    }
    __syncthreads();

    wmma::fragment<wmma::accumulator, 16, 16, 16, float> acc[2][3];
    #pragma unroll
    for (int mt = 0; mt < 2; mt++)
        #pragma unroll
        for (int nt = 0; nt < 3; nt++) wmma::fill_fragment(acc[mt][nt], 0.0f);

    #pragma unroll
    for (int kt = 0; kt < 5; kt++) {
        int cur = kt & 1;
        if (kt < 4) {
            int nxt = cur ^ 1;
            __nv_bfloat16* dh = Ah + nxt * (BM * A_LD);
            __nv_bfloat16* dl = Al + nxt * (BM * A_LD);
            for (int i = threadIdx.x; i < BM * 4; i += 256) {
                int r = i >> 2, c = i & 3;
                size_t goff = (size_t)(row0 + r) * KK + (kt + 1) * 32 + c * 8;
                reinterpret_cast<uint4*>(dh + r * A_LD)[c] =
                    *reinterpret_cast<const uint4*>(g_Xh + goff);
                reinterpret_cast<uint4*>(dl + r * A_LD)[c] =
                    *reinterpret_cast<const uint4*>(g_Xl + goff);
            }
        }
        const __nv_bfloat16* Ahc = Ah + cur * (BM * A_LD);
        const __nv_bfloat16* Alc = Al + cur * (BM * A_LD);

        #pragma unroll
        for (int ks = 0; ks < 32; ks += 16) {
            wmma::fragment<wmma::matrix_a, 16, 16, 16, __nv_bfloat16, wmma::row_major> ah[2], al[2];
            #pragma unroll
            for (int mt = 0; mt < 2; mt++) {
                int arow = wm * 32 + mt * 16;
                wmma::load_matrix_sync(ah[mt], Ahc + arow * A_LD + ks, A_LD);
                wmma::load_matrix_sync(al[mt], Alc + arow * A_LD + ks, A_LD);
            }
            #pragma unroll
            for (int nt = 0; nt < 3; nt++) {
                int bcol = wn * 48 + nt * 16;
                wmma::fragment<wmma::matrix_b, 16, 16, 16, __nv_bfloat16, wmma::row_major> bh, bl;
                wmma::load_matrix_sync(bh, Bh + (kt * 32 + ks) * B_LD + bcol, B_LD);
                wmma::load_matrix_sync(bl, Bl + (kt * 32 + ks) * B_LD + bcol, B_LD);
                #pragma unroll
                for (int mt = 0; mt < 2; mt++) {
                    wmma::mma_sync(acc[mt][nt], ah[mt], bh, acc[mt][nt]);
                    wmma::mma_sync(acc[mt][nt], ah[mt], bl, acc[mt][nt]);
                    wmma::mma_sync(acc[mt][nt], al[mt], bh, acc[mt][nt]);
                }
            }
        }
        __syncthreads();
    }

    #pragma unroll
    for (int mt = 0; mt < 2; mt++)
        #pragma unroll
        for (int nt = 0; nt < 3; nt++)
            wmma::store_matrix_sync(Cs + (wm * 32 + mt * 16) * CN + wn * 48 + nt * 16,
                                    acc[mt][nt], CN, wmma::mem_row_major);
    __syncthreads();

    float relD = 0.0f;
    if (DOT) relD = g_rel[(NL - 1) * Dd + lane];

    for (int i = threadIdx.x; i < BM * Dd; i += 256) {
        int r = i >> 5, d = i & 31;
        int n = row0 + r;
        float v = 0.0f;
        bool ok = (n < Nn);
        if (ok) {
            float s = g_scale[n];
            float inv = 1.0f / fmaxf(s, 0.01f);
            v = Cs[r * CN + d] + s * Cs[r * CN + 32 + d] + inv * Cs[r * CN + 64 + d]
                + linb[layer * Dd + d];
            v = fmaxf(v, 0.0f);
            hout[n * Dd + d] = v;
        }
        if (DOT) {
            float dv = v * relD;
            #pragma unroll
            for (int o = 16; o; o >>= 1) dv += __shfl_xor_sync(0xffffffffu, dv, o);
            if (ok && lane == 0) g_D[n] = dv;
        }
    }
}

// ---------------- final MLP + output assembly + counter reset ----------------
__global__ void k_final(int insel, const float* __restrict__ q,
                        const float* __restrict__ W1, const float* __restrict__ b1,
                        const float* __restrict__ W2, const float* __restrict__ b2,
                        float* __restrict__ out) {
    __shared__ float sW1[64 * 64];
    __shared__ float sW2[64];
    __shared__ float sb1[64];
    __shared__ float sq[32];
    int tid = threadIdx.x;
    int gtid = blockIdx.x * blockDim.x + tid;

    if (gtid < Nn) {
        g_deg[gtid] = 0.0f;
        g_indeg[gtid] = 0;
    }
    if (gtid == 0) { g_sum = 0.0f; g_tot = 0; }

    for (int i = tid; i < 4096; i += 256) sW1[i] = W1[i];
    if (tid < 64) { sW2[tid] = W2[tid]; sb1[tid] = b1[tid]; }
    if (tid < 32) sq[tid] = q[tid];
    __syncthreads();

    const float* __restrict__ hfin = hbuf(insel);
    int warp = gtid >> 5;
    int lane = tid & 31;
    if (warp >= Nn) return;
    int n = warp;
    float hv = hfin[n * Dd + lane];
    float a0 = sb1[lane], a1 = sb1[lane + 32];
    #pragma unroll
    for (int k = 0; k < 32; k++) {
        float xv = __shfl_sync(0xffffffffu, hv, k);
        a0 += xv * sW1[k * 64 + lane];
        a1 += xv * sW1[k * 64 + 32 + lane];
    }
    #pragma unroll
    for (int k = 0; k < 32; k++) {
        float xv = sq[k];
        a0 += xv * sW1[(32 + k) * 64 + lane];
        a1 += xv * sW1[(32 + k) * 64 + 32 + lane];
    }
    a0 = fmaxf(a0, 0.0f);
    a1 = fmaxf(a1, 0.0f);
    float p = a0 * sW2[lane] + a1 * sW2[lane + 32];
    #pragma unroll
    for (int o = 16; o; o >>= 1) p += __shfl_xor_sync(0xffffffffu, p, o);
    if (lane == 0) {
        out[n] = p + b2[0];
        out[Nn + n] = (float)g_pred[n];
    }
}

// ---------------- launch ----------------
extern "C" void kernel_launch(void* const* d_in, const int* in_sizes, int n_in,
                              void* d_out, int out_size) {
    const int*   node_in  = (const int*)d_in[0];
    const int*   node_out = (const int*)d_in[1];
    const float* ew       = (const float*)d_in[2];
    const int*   hptr     = (const int*)d_in[3];
    const float* qw       = (const float*)d_in[4];
    const float* relW     = (const float*)d_in[5];
    const float* relb     = (const float*)d_in[6];
    const float* linW     = (const float*)d_in[7];
    const float* linb     = (const float*)d_in[8];
    const float* W1       = (const float*)d_in[9];
    const float* b1       = (const float*)d_in[10];
    const float* W2       = (const float*)d_in[11];
    const float* b2       = (const float*)d_in[12];
    float* out = (float*)d_out;

    static bool attr_set = false;
    if (!attr_set) {
        cudaFuncSetAttribute(k_gemm<0>, cudaFuncAttributeMaxDynamicSharedMemorySize, GEMM_SMEM);
        cudaFuncSetAttribute(k_gemm<1>, cudaFuncAttributeMaxDynamicSharedMemorySize, GEMM_SMEM);
        attr_set = true;
    }

    k_init<<<(Nn * Dd + 255) / 256, 256>>>(hptr, qw, relW, relb, linW, node_out, ew);
    k_alloc<<<(Nn + 255) / 256, 256>>>();
    k_scatter<<<(Ee + 255) / 256, 256>>>(node_out, node_in, ew);

    int cur = 0;
    for (int l = 0; l < NL; l++) {
        if (l == NL - 1) k_agg<1><<<(Nn + 7) / 8, 256>>>(hptr, cur, l);
        else             k_agg<0><<<(Nn + 7) / 8, 256>>>(hptr, cur, l);
        if (l == NL - 2) k_gemm<1><<<(NR / BM), 256, GEMM_SMEM>>>(linb, l, cur ^ 1);
        else             k_gemm<0><<<(NR / BM), 256, GEMM_SMEM>>>(linb, l, cur ^ 1);
        cur ^= 1;
    }
    k_final<<<(Nn + 7) / 8, 256>>>(cur, qw, W1, b1, W2, b2, out);
}

// round 15
// speedup vs baseline: 1.0271x; 1.0271x over previous
#include <cuda_runtime.h>
#include <cuda_bf16.h>
#include <mma.h>
#include <math.h>

using namespace nvcuda;

#define Nn 50000
#define NR 50048
#define Ee 800000
#define Dd 32
#define NL 6
#define KK 160
#define CN 96
#define BM 128
#define A_LD 40
#define B_LD 104
#define GEMM_SMEM ((2*KK*B_LD + 4*BM*A_LD) * 2)   // 107520 bytes

// ---------------- device scratch ----------------
// g_deg/g_indeg/g_sum/g_tot are zero on first use and re-zeroed in k_final.
__device__ float g_h0[Nn * Dd];
__device__ float g_h1[Nn * Dd];
__device__ __nv_bfloat16 g_Xh[NR * KK];
__device__ __nv_bfloat16 g_Xl[NR * KK];
__device__ __nv_bfloat16 g_Wbh[NL * KK * CN];
__device__ __nv_bfloat16 g_Wbl[NL * KK * CN];
__device__ float g_scale[Nn];
__device__ float g_deg[Nn];
__device__ int   g_indeg[Nn];
__device__ int   g_start[Nn];
__device__ int   g_cursor[Nn];
__device__ int2  g_csr[Ee];
__device__ float g_rel[NL * Dd];
__device__ float g_D[Nn];
__device__ float g_sum;
__device__ int   g_tot;
__device__ int   g_pred[Nn];

__device__ __forceinline__ float* hbuf(int s) { return s ? g_h1 : g_h0; }

// ------- init + edge count fused; boundary fill vectorized (float4) ------
// Grid covers Ee (800K threads); boundary fill uses Nn*Dd/4 = 400K float4 stores.
__global__ void k_init(const int* __restrict__ hptr, const float* __restrict__ q,
                       const float* __restrict__ relW, const float* __restrict__ relb,
                       const float* __restrict__ linW,
                       const int* __restrict__ node_out, const float* __restrict__ ew) {
    int idx = blockIdx.x * blockDim.x + threadIdx.x;
    if (idx < Nn * Dd / 4) {
        int n = idx >> 3;               // 8 float4 per node (32 dims)
        int h = *hptr;
        float bv = (n == h) ? 0.0f : 100.0f;
        reinterpret_cast<float4*>(g_h0)[idx] = make_float4(bv, bv, bv, bv);
    }
    if (idx < NL * KK * CN) {
        int l = idx / (KK * CN);
        int rem = idx % (KK * CN);
        int k = rem / CN;
        int j = rem % CN;
        float v;
        if (k < 32) {
            v = (j < 32) ? linW[(l * 416 + k) * 32 + j] : 0.0f;
        } else {
            int f = k - 32, g = j >> 5, d = j & 31;
            v = linW[(l * 416 + 32 + f * 3 + g) * 32 + d];
        }
        __nv_bfloat16 hh = __float2bfloat16_rn(v);
        g_Wbh[idx] = hh;
        g_Wbl[idx] = __float2bfloat16_rn(v - __bfloat162float(hh));
    }
    if (idx < NL * Dd) {
        int i = idx >> 5, d = idx & 31;
        float acc = relb[i * Dd + d];
        for (int k = 0; k < Dd; k++)
            acc += q[k] * relW[(i * Dd + k) * Dd + d];
        g_rel[i * Dd + d] = acc;
    }
    if (idx < Ee) {
        int o = node_out[idx];
        atomicAdd(&g_deg[o], ew[idx]);
        atomicAdd(&g_indeg[o], 1);
    }
}

// ---------------- segment allocation + log(deg) partial sum ----------------
__global__ void k_alloc() {
    int i = blockIdx.x * blockDim.x + threadIdx.x;
    float s = 0.0f;
    if (i < Nn) {
        int c = g_indeg[i];
        int st = atomicAdd(&g_tot, c);
        g_start[i] = st;
        g_cursor[i] = st;
        s = logf(g_deg[i] + 1.0f);
        g_scale[i] = s;
    }
    for (int o = 16; o; o >>= 1) s += __shfl_xor_sync(0xffffffffu, s, o);
    __shared__ float wsum[8];
    int lane = threadIdx.x & 31, wid = threadIdx.x >> 5;
    if (lane == 0) wsum[wid] = s;
    __syncthreads();
    if (threadIdx.x == 0) {
        float t = 0.0f;
        for (int w = 0; w < 8; w++) t += wsum[w];
        atomicAdd(&g_sum, t);
    }
}

// ---------------- CSR scatter + scale normalize ----------------
__global__ void k_scatter(const int* __restrict__ node_out, const int* __restrict__ node_in,
                          const float* __restrict__ ew) {
    int e = blockIdx.x * blockDim.x + threadIdx.x;
    if (e < Nn) g_scale[e] = g_scale[e] * ((float)Nn / g_sum);
    if (e >= Ee) return;
    int n = node_out[e];
    int p = atomicAdd(&g_cursor[n], 1);
    g_csr[p] = make_int2(node_in[e], __float_as_int(ew[e]));
}

// ---------------- aggregation: warp per node, lane = dim, MLP=4,
// shfl-staged CSR (prefetch into registers), rel factored out ----------------
template <int LAST>
__global__ void __launch_bounds__(256, 8)
k_agg(const int* __restrict__ hptr, int insel, int layer) {
    int warp = (blockIdx.x * blockDim.x + threadIdx.x) >> 5;
    int lane = threadIdx.x & 31;
    if (warp >= Nn) return;
    int n = warp;
    const float* __restrict__ hin = hbuf(insel);
    int h = *hptr;
    float relv = g_rel[layer * Dd + lane];
    const float INF = __int_as_float(0x7f800000);

    float b = (n == h) ? 0.0f : 100.0f;
    float sumv = 0.0f, sqv = 0.0f, mxv = -INF, mnv = INF;
    float bestS = 32.0f * b;
    int bestSrc = n;

    int st = g_start[n];
    int cnt = g_indeg[n];
    for (int base = 0; base < cnt; base += 32) {
        int rem = cnt - base;
        int m = rem < 32 ? rem : 32;
        int2 ed = make_int2(0, 0);
        if (lane < m) ed = g_csr[st + base + lane];

        int j = 0;
        for (; j + 4 <= m; j += 4) {
            int s0 = __shfl_sync(0xffffffffu, ed.x, j + 0);
            int s1 = __shfl_sync(0xffffffffu, ed.x, j + 1);
            int s2 = __shfl_sync(0xffffffffu, ed.x, j + 2);
            int s3 = __shfl_sync(0xffffffffu, ed.x, j + 3);
            float w0 = __int_as_float(__shfl_sync(0xffffffffu, ed.y, j + 0));
            float w1 = __int_as_float(__shfl_sync(0xffffffffu, ed.y, j + 1));
            float w2 = __int_as_float(__shfl_sync(0xffffffffu, ed.y, j + 2));
            float w3 = __int_as_float(__shfl_sync(0xffffffffu, ed.y, j + 3));
            float v0 = hin[s0 * Dd + lane];
            float v1 = hin[s1 * Dd + lane];
            float v2 = hin[s2 * Dd + lane];
            float v3 = hin[s3 * Dd + lane];
            float D0 = 0.f, D1 = 0.f, D2 = 0.f, D3 = 0.f;
            if (LAST) { D0 = g_D[s0]; D1 = g_D[s1]; D2 = g_D[s2]; D3 = g_D[s3]; }

            float wv0 = v0 * w0;
            sumv += wv0; sqv += v0 * wv0;
            mxv = fmaxf(mxv, wv0); mnv = fminf(mnv, wv0);
            float wv1 = v1 * w1;
            sumv += wv1; sqv += v1 * wv1;
            mxv = fmaxf(mxv, wv1); mnv = fminf(mnv, wv1);
            float wv2 = v2 * w2;
            sumv += wv2; sqv += v2 * wv2;
            mxv = fmaxf(mxv, wv2); mnv = fminf(mnv, wv2);
            float wv3 = v3 * w3;
            sumv += wv3; sqv += v3 * wv3;
            mxv = fmaxf(mxv, wv3); mnv = fminf(mnv, wv3);

            if (LAST) {
                float sc0 = w0 * D0, sc1 = w1 * D1, sc2 = w2 * D2, sc3 = w3 * D3;
                if (sc0 > bestS) { bestS = sc0; bestSrc = s0; }
                else if (sc0 == bestS) bestSrc = min(bestSrc, s0);
                if (sc1 > bestS) { bestS = sc1; bestSrc = s1; }
                else if (sc1 == bestS) bestSrc = min(bestSrc, s1);
                if (sc2 > bestS) { bestS = sc2; bestSrc = s2; }
                else if (sc2 == bestS) bestSrc = min(bestSrc, s2);
                if (sc3 > bestS) { bestS = sc3; bestSrc = s3; }
                else if (sc3 == bestS) bestSrc = min(bestSrc, s3);
            }
        }
        for (; j < m; j++) {
            int s0 = __shfl_sync(0xffffffffu, ed.x, j);
            float w0 = __int_as_float(__shfl_sync(0xffffffffu, ed.y, j));
            float v0 = hin[s0 * Dd + lane];
            float wv0 = v0 * w0;
            sumv += wv0; sqv += v0 * wv0;
            mxv = fmaxf(mxv, wv0); mnv = fminf(mnv, wv0);
            if (LAST) {
                float sc = w0 * g_D[s0];
                if (sc > bestS) { bestS = sc; bestSrc = s0; }
                else if (sc == bestS) bestSrc = min(bestSrc, s0);
            }
        }
    }

    float sum = relv * sumv + b;
    float sq = relv * relv * sqv + b * b;
    float mx, mn;
    if (cnt > 0) {
        float emax = (relv >= 0.0f) ? relv * mxv : relv * mnv;
        float emin = (relv >= 0.0f) ? relv * mnv : relv * mxv;
        mx = fmaxf(emax, b);
        mn = fminf(emin, b);
    } else {
        mx = b; mn = b;
    }

    float c = (float)(cnt + 1);
    float mean = sum / c;
    float sqm = sq / c;
    float sd = sqrtf(fmaxf(sqm - mean * mean, 1e-6f));

    float hv = hin[n * Dd + lane];
    __nv_bfloat16 hh = __float2bfloat16_rn(hv);
    g_Xh[n * KK + lane] = hh;
    g_Xl[n * KK + lane] = __float2bfloat16_rn(hv - __bfloat162float(hh));

    union { __nv_bfloat16 v[4]; uint2 u; } ph, pl;
    float fv[4] = {mean, mx, mn, sd};
    #pragma unroll
    for (int t = 0; t < 4; t++) {
        __nv_bfloat16 fh = __float2bfloat16_rn(fv[t]);
        ph.v[t] = fh;
        pl.v[t] = __float2bfloat16_rn(fv[t] - __bfloat162float(fh));
    }
    *reinterpret_cast<uint2*>(&g_Xh[n * KK + Dd + lane * 4]) = ph.u;
    *reinterpret_cast<uint2*>(&g_Xl[n * KK + Dd + lane * 4]) = pl.u;

    if (LAST && lane == 0) g_pred[n] = bestSrc;
}

// ---------------- tensor-core GEMM (BM=128, 2x3 warp tile, dbl-buffered A) ----
template <int DOT>
__global__ void k_gemm(const float* __restrict__ linb, int layer, int outsel) {
    extern __shared__ char sm_[];
    __nv_bfloat16* Bh = reinterpret_cast<__nv_bfloat16*>(sm_);
    __nv_bfloat16* Bl = Bh + KK * B_LD;
    __nv_bfloat16* Ah = Bl + KK * B_LD;
    __nv_bfloat16* Al = Ah + 2 * BM * A_LD;
    float* Cs = reinterpret_cast<float*>(sm_);

    float* __restrict__ hout = hbuf(outsel);
    int row0 = blockIdx.x * BM;
    int wid = threadIdx.x >> 5;
    int lane = threadIdx.x & 31;
    int wm = wid >> 1;
    int wn = wid & 1;

    {
        const uint4* srcH = reinterpret_cast<const uint4*>(g_Wbh + layer * KK * CN);
        const uint4* srcL = reinterpret_cast<const uint4*>(g_Wbl + layer * KK * CN);
        for (int i = threadIdx.x; i < KK * CN / 8; i += 256) {
            int r = i / 12, c = i % 12;
            reinterpret_cast<uint4*>(Bh + r * B_LD)[c] = srcH[i];
            reinterpret_cast<uint4*>(Bl + r * B_LD)[c] = srcL[i];
        }
    }
    {
        for (int i = threadIdx.x; i < BM * 4; i += 256) {
            int r = i >> 2, c = i & 3;
            size_t goff = (size_t)(row0 + r) * KK + c * 8;
            reinterpret_cast<uint4*>(Ah + r * A_LD)[c] =
                *reinterpret_cast<const uint4*>(g_Xh + goff);
            reinterpret_cast<uint4*>(Al + r * A_LD)[c] =
                *reinterpret_cast<const uint4*>(g_Xl + goff);
        }
    }
    __syncthreads();

    wmma::fragment<wmma::accumulator, 16, 16, 16, float> acc[2][3];
    #pragma unroll
    for (int mt = 0; mt < 2; mt++)
        #pragma unroll
        for (int nt = 0; nt < 3; nt++) wmma::fill_fragment(acc[mt][nt], 0.0f);

    #pragma unroll
    for (int kt = 0; kt < 5; kt++) {
        int cur = kt & 1;
        if (kt < 4) {
            int nxt = cur ^ 1;
            __nv_bfloat16* dh = Ah + nxt * (BM * A_LD);
            __nv_bfloat16* dl = Al + nxt * (BM * A_LD);
            for (int i = threadIdx.x; i < BM * 4; i += 256) {
                int r = i >> 2, c = i & 3;
                size_t goff = (size_t)(row0 + r) * KK + (kt + 1) * 32 + c * 8;
                reinterpret_cast<uint4*>(dh + r * A_LD)[c] =
                    *reinterpret_cast<const uint4*>(g_Xh + goff);
                reinterpret_cast<uint4*>(dl + r * A_LD)[c] =
                    *reinterpret_cast<const uint4*>(g_Xl + goff);
            }
        }
        const __nv_bfloat16* Ahc = Ah + cur * (BM * A_LD);
        const __nv_bfloat16* Alc = Al + cur * (BM * A_LD);

        #pragma unroll
        for (int ks = 0; ks < 32; ks += 16) {
            wmma::fragment<wmma::matrix_a, 16, 16, 16, __nv_bfloat16, wmma::row_major> ah[2], al[2];
            #pragma unroll
            for (int mt = 0; mt < 2; mt++) {
                int arow = wm * 32 + mt * 16;
                wmma::load_matrix_sync(ah[mt], Ahc + arow * A_LD + ks, A_LD);
                wmma::load_matrix_sync(al[mt], Alc + arow * A_LD + ks, A_LD);
            }
            #pragma unroll
            for (int nt = 0; nt < 3; nt++) {
                int bcol = wn * 48 + nt * 16;
                wmma::fragment<wmma::matrix_b, 16, 16, 16, __nv_bfloat16, wmma::row_major> bh, bl;
                wmma::load_matrix_sync(bh, Bh + (kt * 32 + ks) * B_LD + bcol, B_LD);
                wmma::load_matrix_sync(bl, Bl + (kt * 32 + ks) * B_LD + bcol, B_LD);
                #pragma unroll
                for (int mt = 0; mt < 2; mt++) {
                    wmma::mma_sync(acc[mt][nt], ah[mt], bh, acc[mt][nt]);
                    wmma::mma_sync(acc[mt][nt], ah[mt], bl, acc[mt][nt]);
                    wmma::mma_sync(acc[mt][nt], al[mt], bh, acc[mt][nt]);
                }
            }
        }
        __syncthreads();
    }

    #pragma unroll
    for (int mt = 0; mt < 2; mt++)
        #pragma unroll
        for (int nt = 0; nt < 3; nt++)
            wmma::store_matrix_sync(Cs + (wm * 32 + mt * 16) * CN + wn * 48 + nt * 16,
                                    acc[mt][nt], CN, wmma::mem_row_major);
    __syncthreads();

    float relD = 0.0f;
    if (DOT) relD = g_rel[(NL - 1) * Dd + lane];

    for (int i = threadIdx.x; i < BM * Dd; i += 256) {
        int r = i >> 5, d = i & 31;
        int n = row0 + r;
        float v = 0.0f;
        bool ok = (n < Nn);
        if (ok) {
            float s = g_scale[n];
            float inv = 1.0f / fmaxf(s, 0.01f);
            v = Cs[r * CN + d] + s * Cs[r * CN + 32 + d] + inv * Cs[r * CN + 64 + d]
                + linb[layer * Dd + d];
            v = fmaxf(v, 0.0f);
            hout[n * Dd + d] = v;
        }
        if (DOT) {
            float dv = v * relD;
            #pragma unroll
            for (int o = 16; o; o >>= 1) dv += __shfl_xor_sync(0xffffffffu, dv, o);
            if (ok && lane == 0) g_D[n] = dv;
        }
    }
}

// ---------------- final MLP + output assembly + counter reset ----------------
__global__ void k_final(int insel, const float* __restrict__ q,
                        const float* __restrict__ W1, const float* __restrict__ b1,
                        const float* __restrict__ W2, const float* __restrict__ b2,
                        float* __restrict__ out) {
    __shared__ float sW1[64 * 64];
    __shared__ float sW2[64];
    __shared__ float sb1[64];
    __shared__ float sq[32];
    int tid = threadIdx.x;
    int gtid = blockIdx.x * blockDim.x + tid;

    if (gtid < Nn) {
        g_deg[gtid] = 0.0f;
        g_indeg[gtid] = 0;
    }
    if (gtid == 0) { g_sum = 0.0f; g_tot = 0; }

    for (int i = tid; i < 4096; i += 256) sW1[i] = W1[i];
    if (tid < 64) { sW2[tid] = W2[tid]; sb1[tid] = b1[tid]; }
    if (tid < 32) sq[tid] = q[tid];
    __syncthreads();

    const float* __restrict__ hfin = hbuf(insel);
    int warp = gtid >> 5;
    int lane = tid & 31;
    if (warp >= Nn) return;
    int n = warp;
    float hv = hfin[n * Dd + lane];
    float a0 = sb1[lane], a1 = sb1[lane + 32];
    #pragma unroll
    for (int k = 0; k < 32; k++) {
        float xv = __shfl_sync(0xffffffffu, hv, k);
        a0 += xv * sW1[k * 64 + lane];
        a1 += xv * sW1[k * 64 + 32 + lane];
    }
    #pragma unroll
    for (int k = 0; k < 32; k++) {
        float xv = sq[k];
        a0 += xv * sW1[(32 + k) * 64 + lane];
        a1 += xv * sW1[(32 + k) * 64 + 32 + lane];
    }
    a0 = fmaxf(a0, 0.0f);
    a1 = fmaxf(a1, 0.0f);
    float p = a0 * sW2[lane] + a1 * sW2[lane + 32];
    #pragma unroll
    for (int o = 16; o; o >>= 1) p += __shfl_xor_sync(0xffffffffu, p, o);
    if (lane == 0) {
        out[n] = p + b2[0];
        out[Nn + n] = (float)g_pred[n];
    }
}

// ---------------- launch ----------------
extern "C" void kernel_launch(void* const* d_in, const int* in_sizes, int n_in,
                              void* d_out, int out_size) {
    const int*   node_in  = (const int*)d_in[0];
    const int*   node_out = (const int*)d_in[1];
    const float* ew       = (const float*)d_in[2];
    const int*   hptr     = (const int*)d_in[3];
    const float* qw       = (const float*)d_in[4];
    const float* relW     = (const float*)d_in[5];
    const float* relb     = (const float*)d_in[6];
    const float* linW     = (const float*)d_in[7];
    const float* linb     = (const float*)d_in[8];
    const float* W1       = (const float*)d_in[9];
    const float* b1       = (const float*)d_in[10];
    const float* W2       = (const float*)d_in[11];
    const float* b2       = (const float*)d_in[12];
    float* out = (float*)d_out;

    static bool attr_set = false;
    if (!attr_set) {
        cudaFuncSetAttribute(k_gemm<0>, cudaFuncAttributeMaxDynamicSharedMemorySize, GEMM_SMEM);
        cudaFuncSetAttribute(k_gemm<1>, cudaFuncAttributeMaxDynamicSharedMemorySize, GEMM_SMEM);
        attr_set = true;
    }

    k_init<<<(Ee + 255) / 256, 256>>>(hptr, qw, relW, relb, linW, node_out, ew);
    k_alloc<<<(Nn + 255) / 256, 256>>>();
    k_scatter<<<(Ee + 255) / 256, 256>>>(node_out, node_in, ew);

    int cur = 0;
    for (int l = 0; l < NL; l++) {
        if (l == NL - 1) k_agg<1><<<(Nn + 7) / 8, 256>>>(hptr, cur, l);
        else             k_agg<0><<<(Nn + 7) / 8, 256>>>(hptr, cur, l);
        if (l == NL - 2) k_gemm<1><<<(NR / BM), 256, GEMM_SMEM>>>(linb, l, cur ^ 1);
        else             k_gemm<0><<<(NR / BM), 256, GEMM_SMEM>>>(linb, l, cur ^ 1);
        cur ^= 1;
    }
    k_final<<<(Nn + 7) / 8, 256>>>(cur, qw, W1, b1, W2, b2, out);
}

// round 16
// speedup vs baseline: 1.0610x; 1.0330x over previous
#include <cuda_runtime.h>
#include <cuda_bf16.h>
#include <mma.h>
#include <math.h>

using namespace nvcuda;

#define Nn 50000
#define NR 50048
#define Ee 800000
#define Dd 32
#define NL 6
#define KK 160
#define CN 96
#define BM 128
#define A_LD 40
#define B_LD 104
#define GEMM_SMEM ((2*KK*B_LD + 4*BM*A_LD) * 2)   // 107520 bytes

// ---------------- device scratch ----------------
// g_deg/g_indeg/g_sum/g_tot are zero on first use and re-zeroed in k_final.
__device__ float g_h0[Nn * Dd];
__device__ float g_h1[Nn * Dd];
__device__ __nv_bfloat16 g_Xh[NR * KK];
__device__ __nv_bfloat16 g_Xl[NR * KK];
__device__ __nv_bfloat16 g_Wbh[NL * KK * CN];
__device__ __nv_bfloat16 g_Wbl[NL * KK * CN];
__device__ float g_scale[Nn];
__device__ float g_deg[Nn];
__device__ int   g_indeg[Nn];
__device__ int   g_start[Nn];
__device__ int   g_cursor[Nn];
__device__ int2  g_csr[Ee];
__device__ float g_rel[NL * Dd];
__device__ float g_D[Nn];
__device__ float g_sum;
__device__ int   g_tot;
__device__ int   g_pred[Nn];

__device__ __forceinline__ float* hbuf(int s) { return s ? g_h1 : g_h0; }

// ------- init + edge count fused; boundary fill vectorized (float4) ------
__global__ void k_init(const int* __restrict__ hptr, const float* __restrict__ q,
                       const float* __restrict__ relW, const float* __restrict__ relb,
                       const float* __restrict__ linW,
                       const int* __restrict__ node_out, const float* __restrict__ ew) {
    int idx = blockIdx.x * blockDim.x + threadIdx.x;
    if (idx < Nn * Dd / 4) {
        int n = idx >> 3;
        int h = *hptr;
        float bv = (n == h) ? 0.0f : 100.0f;
        reinterpret_cast<float4*>(g_h0)[idx] = make_float4(bv, bv, bv, bv);
    }
    if (idx < NL * KK * CN) {
        int l = idx / (KK * CN);
        int rem = idx % (KK * CN);
        int k = rem / CN;
        int j = rem % CN;
        float v;
        if (k < 32) {
            v = (j < 32) ? linW[(l * 416 + k) * 32 + j] : 0.0f;
        } else {
            int f = k - 32, g = j >> 5, d = j & 31;
            v = linW[(l * 416 + 32 + f * 3 + g) * 32 + d];
        }
        __nv_bfloat16 hh = __float2bfloat16_rn(v);
        g_Wbh[idx] = hh;
        g_Wbl[idx] = __float2bfloat16_rn(v - __bfloat162float(hh));
    }
    if (idx < NL * Dd) {
        int i = idx >> 5, d = idx & 31;
        float acc = relb[i * Dd + d];
        for (int k = 0; k < Dd; k++)
            acc += q[k] * relW[(i * Dd + k) * Dd + d];
        g_rel[i * Dd + d] = acc;
    }
    if (idx < Ee) {
        int o = node_out[idx];
        atomicAdd(&g_deg[o], ew[idx]);
        atomicAdd(&g_indeg[o], 1);
    }
}

// ---------------- segment allocation + log(deg) partial sum ----------------
__global__ void k_alloc() {
    int i = blockIdx.x * blockDim.x + threadIdx.x;
    float s = 0.0f;
    if (i < Nn) {
        int c = g_indeg[i];
        int st = atomicAdd(&g_tot, c);
        g_start[i] = st;
        g_cursor[i] = st;
        s = logf(g_deg[i] + 1.0f);
        g_scale[i] = s;
    }
    for (int o = 16; o; o >>= 1) s += __shfl_xor_sync(0xffffffffu, s, o);
    __shared__ float wsum[8];
    int lane = threadIdx.x & 31, wid = threadIdx.x >> 5;
    if (lane == 0) wsum[wid] = s;
    __syncthreads();
    if (threadIdx.x == 0) {
        float t = 0.0f;
        for (int w = 0; w < 8; w++) t += wsum[w];
        atomicAdd(&g_sum, t);
    }
}

// ---------------- CSR scatter + scale normalize ----------------
__global__ void k_scatter(const int* __restrict__ node_out, const int* __restrict__ node_in,
                          const float* __restrict__ ew) {
    int e = blockIdx.x * blockDim.x + threadIdx.x;
    if (e < Nn) g_scale[e] = g_scale[e] * ((float)Nn / g_sum);
    if (e >= Ee) return;
    int n = node_out[e];
    int p = atomicAdd(&g_cursor[n], 1);
    g_csr[p] = make_int2(node_in[e], __float_as_int(ew[e]));
}

// ---------------- shared epilogue: apply rel, fold boundary, write X ----------
__device__ __forceinline__ void agg_epilogue(
    int n, int lane, int cnt, float b, float relv,
    float sumv, float sqv, float mxv, float mnv, float hv) {
    float sum = relv * sumv + b;
    float sq = relv * relv * sqv + b * b;
    float mx, mn;
    if (cnt > 0) {
        float emax = (relv >= 0.0f) ? relv * mxv : relv * mnv;
        float emin = (relv >= 0.0f) ? relv * mnv : relv * mxv;
        mx = fmaxf(emax, b);
        mn = fminf(emin, b);
    } else {
        mx = b; mn = b;
    }

    float c = (float)(cnt + 1);
    float mean = sum / c;
    float sqm = sq / c;
    float sd = sqrtf(fmaxf(sqm - mean * mean, 1e-6f));

    __nv_bfloat16 hh = __float2bfloat16_rn(hv);
    g_Xh[n * KK + lane] = hh;
    g_Xl[n * KK + lane] = __float2bfloat16_rn(hv - __bfloat162float(hh));

    union { __nv_bfloat16 v[4]; uint2 u; } ph, pl;
    float fv[4] = {mean, mx, mn, sd};
    #pragma unroll
    for (int t = 0; t < 4; t++) {
        __nv_bfloat16 fh = __float2bfloat16_rn(fv[t]);
        ph.v[t] = fh;
        pl.v[t] = __float2bfloat16_rn(fv[t] - __bfloat162float(fh));
    }
    *reinterpret_cast<uint2*>(&g_Xh[n * KK + Dd + lane * 4]) = ph.u;
    *reinterpret_cast<uint2*>(&g_Xl[n * KK + Dd + lane * 4]) = pl.u;
}

// ---------------- layer-0 aggregation: boundary input is LANE-UNIFORM,
// so each lane reduces its own edges (no gather, no per-edge serial loop) ------
__global__ void __launch_bounds__(256, 8)
k_agg0(const int* __restrict__ hptr) {
    int warp = (blockIdx.x * blockDim.x + threadIdx.x) >> 5;
    int lane = threadIdx.x & 31;
    if (warp >= Nn) return;
    int n = warp;
    int h = *hptr;
    float relv = g_rel[lane];   // layer 0
    const float INF = __int_as_float(0x7f800000);

    float b = (n == h) ? 0.0f : 100.0f;
    float sumv = 0.0f, sqv = 0.0f, mxv = -INF, mnv = INF;

    int st = g_start[n];
    int cnt = g_indeg[n];
    for (int base = 0; base < cnt; base += 32) {
        int m = cnt - base; if (m > 32) m = 32;
        if (lane < m) {
            int2 ed = g_csr[st + base + lane];
            float w = __int_as_float(ed.y);
            float v = (ed.x == h) ? 0.0f : 100.0f;
            float wv = v * w;
            sumv += wv; sqv += v * wv;
            mxv = fmaxf(mxv, wv); mnv = fminf(mnv, wv);
        }
    }
    // warp allreduce (all lanes get the totals)
    #pragma unroll
    for (int o = 16; o; o >>= 1) {
        sumv += __shfl_xor_sync(0xffffffffu, sumv, o);
        sqv  += __shfl_xor_sync(0xffffffffu, sqv, o);
        mxv = fmaxf(mxv, __shfl_xor_sync(0xffffffffu, mxv, o));
        mnv = fminf(mnv, __shfl_xor_sync(0xffffffffu, mnv, o));
    }

    agg_epilogue(n, lane, cnt, b, relv, sumv, sqv, mxv, mnv, /*hv=*/b);
}

// ---------------- aggregation layers 1..5: warp per node, lane = dim, MLP=4,
// shfl-staged CSR prefetch, rel factored out ----------------
template <int LAST>
__global__ void __launch_bounds__(256, 8)
k_agg(const int* __restrict__ hptr, int insel, int layer) {
    int warp = (blockIdx.x * blockDim.x + threadIdx.x) >> 5;
    int lane = threadIdx.x & 31;
    if (warp >= Nn) return;
    int n = warp;
    const float* __restrict__ hin = hbuf(insel);
    int h = *hptr;
    float relv = g_rel[layer * Dd + lane];
    const float INF = __int_as_float(0x7f800000);

    float b = (n == h) ? 0.0f : 100.0f;
    float sumv = 0.0f, sqv = 0.0f, mxv = -INF, mnv = INF;
    float bestS = 32.0f * b;
    int bestSrc = n;

    int st = g_start[n];
    int cnt = g_indeg[n];
    for (int base = 0; base < cnt; base += 32) {
        int rem = cnt - base;
        int m = rem < 32 ? rem : 32;
        int2 ed = make_int2(0, 0);
        if (lane < m) ed = g_csr[st + base + lane];

        int j = 0;
        for (; j + 4 <= m; j += 4) {
            int s0 = __shfl_sync(0xffffffffu, ed.x, j + 0);
            int s1 = __shfl_sync(0xffffffffu, ed.x, j + 1);
            int s2 = __shfl_sync(0xffffffffu, ed.x, j + 2);
            int s3 = __shfl_sync(0xffffffffu, ed.x, j + 3);
            float w0 = __int_as_float(__shfl_sync(0xffffffffu, ed.y, j + 0));
            float w1 = __int_as_float(__shfl_sync(0xffffffffu, ed.y, j + 1));
            float w2 = __int_as_float(__shfl_sync(0xffffffffu, ed.y, j + 2));
            float w3 = __int_as_float(__shfl_sync(0xffffffffu, ed.y, j + 3));
            float v0 = hin[s0 * Dd + lane];
            float v1 = hin[s1 * Dd + lane];
            float v2 = hin[s2 * Dd + lane];
            float v3 = hin[s3 * Dd + lane];
            float D0 = 0.f, D1 = 0.f, D2 = 0.f, D3 = 0.f;
            if (LAST) { D0 = g_D[s0]; D1 = g_D[s1]; D2 = g_D[s2]; D3 = g_D[s3]; }

            float wv0 = v0 * w0;
            sumv += wv0; sqv += v0 * wv0;
            mxv = fmaxf(mxv, wv0); mnv = fminf(mnv, wv0);
            float wv1 = v1 * w1;
            sumv += wv1; sqv += v1 * wv1;
            mxv = fmaxf(mxv, wv1); mnv = fminf(mnv, wv1);
            float wv2 = v2 * w2;
            sumv += wv2; sqv += v2 * wv2;
            mxv = fmaxf(mxv, wv2); mnv = fminf(mnv, wv2);
            float wv3 = v3 * w3;
            sumv += wv3; sqv += v3 * wv3;
            mxv = fmaxf(mxv, wv3); mnv = fminf(mnv, wv3);

            if (LAST) {
                float sc0 = w0 * D0, sc1 = w1 * D1, sc2 = w2 * D2, sc3 = w3 * D3;
                if (sc0 > bestS) { bestS = sc0; bestSrc = s0; }
                else if (sc0 == bestS) bestSrc = min(bestSrc, s0);
                if (sc1 > bestS) { bestS = sc1; bestSrc = s1; }
                else if (sc1 == bestS) bestSrc = min(bestSrc, s1);
                if (sc2 > bestS) { bestS = sc2; bestSrc = s2; }
                else if (sc2 == bestS) bestSrc = min(bestSrc, s2);
                if (sc3 > bestS) { bestS = sc3; bestSrc = s3; }
                else if (sc3 == bestS) bestSrc = min(bestSrc, s3);
            }
        }
        for (; j < m; j++) {
            int s0 = __shfl_sync(0xffffffffu, ed.x, j);
            float w0 = __int_as_float(__shfl_sync(0xffffffffu, ed.y, j));
            float v0 = hin[s0 * Dd + lane];
            float wv0 = v0 * w0;
            sumv += wv0; sqv += v0 * wv0;
            mxv = fmaxf(mxv, wv0); mnv = fminf(mnv, wv0);
            if (LAST) {
                float sc = w0 * g_D[s0];
                if (sc > bestS) { bestS = sc; bestSrc = s0; }
                else if (sc == bestS) bestSrc = min(bestSrc, s0);
            }
        }
    }

    float hv = hin[n * Dd + lane];
    agg_epilogue(n, lane, cnt, b, relv, sumv, sqv, mxv, mnv, hv);

    if (LAST && lane == 0) g_pred[n] = bestSrc;
}

// ---------------- tensor-core GEMM (BM=128, 2x3 warp tile, dbl-buffered A) ----
template <int DOT>
__global__ void k_gemm(const float* __restrict__ linb, int layer, int outsel) {
    extern __shared__ char sm_[];
    __nv_bfloat16* Bh = reinterpret_cast<__nv_bfloat16*>(sm_);
    __nv_bfloat16* Bl = Bh + KK * B_LD;
    __nv_bfloat16* Ah = Bl + KK * B_LD;
    __nv_bfloat16* Al = Ah + 2 * BM * A_LD;
    float* Cs = reinterpret_cast<float*>(sm_);

    float* __restrict__ hout = hbuf(outsel);
    int row0 = blockIdx.x * BM;
    int wid = threadIdx.x >> 5;
    int lane = threadIdx.x & 31;
    int wm = wid >> 1;
    int wn = wid & 1;

    {
        const uint4* srcH = reinterpret_cast<const uint4*>(g_Wbh + layer * KK * CN);
        const uint4* srcL = reinterpret_cast<const uint4*>(g_Wbl + layer * KK * CN);
        for (int i = threadIdx.x; i < KK * CN / 8; i += 256) {
            int r = i / 12, c = i % 12;
            reinterpret_cast<uint4*>(Bh + r * B_LD)[c] = srcH[i];
            reinterpret_cast<uint4*>(Bl + r * B_LD)[c] = srcL[i];
        }
    }
    {
        for (int i = threadIdx.x; i < BM * 4; i += 256) {
            int r = i >> 2, c = i & 3;
            size_t goff = (size_t)(row0 + r) * KK + c * 8;
            reinterpret_cast<uint4*>(Ah + r * A_LD)[c] =
                *reinterpret_cast<const uint4*>(g_Xh + goff);
            reinterpret_cast<uint4*>(Al + r * A_LD)[c] =
                *reinterpret_cast<const uint4*>(g_Xl + goff);
        }
    }
    __syncthreads();

    wmma::fragment<wmma::accumulator, 16, 16, 16, float> acc[2][3];
    #pragma unroll
    for (int mt = 0; mt < 2; mt++)
        #pragma unroll
        for (int nt = 0; nt < 3; nt++) wmma::fill_fragment(acc[mt][nt], 0.0f);

    #pragma unroll
    for (int kt = 0; kt < 5; kt++) {
        int cur = kt & 1;
        if (kt < 4) {
            int nxt = cur ^ 1;
            __nv_bfloat16* dh = Ah + nxt * (BM * A_LD);
            __nv_bfloat16* dl = Al + nxt * (BM * A_LD);
            for (int i = threadIdx.x; i < BM * 4; i += 256) {
                int r = i >> 2, c = i & 3;
                size_t goff = (size_t)(row0 + r) * KK + (kt + 1) * 32 + c * 8;
                reinterpret_cast<uint4*>(dh + r * A_LD)[c] =
                    *reinterpret_cast<const uint4*>(g_Xh + goff);
                reinterpret_cast<uint4*>(dl + r * A_LD)[c] =
                    *reinterpret_cast<const uint4*>(g_Xl + goff);
            }
        }
        const __nv_bfloat16* Ahc = Ah + cur * (BM * A_LD);
        const __nv_bfloat16* Alc = Al + cur * (BM * A_LD);

        #pragma unroll
        for (int ks = 0; ks < 32; ks += 16) {
            wmma::fragment<wmma::matrix_a, 16, 16, 16, __nv_bfloat16, wmma::row_major> ah[2], al[2];
            #pragma unroll
            for (int mt = 0; mt < 2; mt++) {
                int arow = wm * 32 + mt * 16;
                wmma::load_matrix_sync(ah[mt], Ahc + arow * A_LD + ks, A_LD);
                wmma::load_matrix_sync(al[mt], Alc + arow * A_LD + ks, A_LD);
            }
            #pragma unroll
            for (int nt = 0; nt < 3; nt++) {
                int bcol = wn * 48 + nt * 16;
                wmma::fragment<wmma::matrix_b, 16, 16, 16, __nv_bfloat16, wmma::row_major> bh, bl;
                wmma::load_matrix_sync(bh, Bh + (kt * 32 + ks) * B_LD + bcol, B_LD);
                wmma::load_matrix_sync(bl, Bl + (kt * 32 + ks) * B_LD + bcol, B_LD);
                #pragma unroll
                for (int mt = 0; mt < 2; mt++) {
                    wmma::mma_sync(acc[mt][nt], ah[mt], bh, acc[mt][nt]);
                    wmma::mma_sync(acc[mt][nt], ah[mt], bl, acc[mt][nt]);
                    wmma::mma_sync(acc[mt][nt], al[mt], bh, acc[mt][nt]);
                }
            }
        }
        __syncthreads();
    }

    #pragma unroll
    for (int mt = 0; mt < 2; mt++)
        #pragma unroll
        for (int nt = 0; nt < 3; nt++)
            wmma::store_matrix_sync(Cs + (wm * 32 + mt * 16) * CN + wn * 48 + nt * 16,
                                    acc[mt][nt], CN, wmma::mem_row_major);
    __syncthreads();

    float relD = 0.0f;
    if (DOT) relD = g_rel[(NL - 1) * Dd + lane];

    for (int i = threadIdx.x; i < BM * Dd; i += 256) {
        int r = i >> 5, d = i & 31;
        int n = row0 + r;
        float v = 0.0f;
        bool ok = (n < Nn);
        if (ok) {
            float s = g_scale[n];
            float inv = 1.0f / fmaxf(s, 0.01f);
            v = Cs[r * CN + d] + s * Cs[r * CN + 32 + d] + inv * Cs[r * CN + 64 + d]
                + linb[layer * Dd + d];
            v = fmaxf(v, 0.0f);
            hout[n * Dd + d] = v;
        }
        if (DOT) {
            float dv = v * relD;
            #pragma unroll
            for (int o = 16; o; o >>= 1) dv += __shfl_xor_sync(0xffffffffu, dv, o);
            if (ok && lane == 0) g_D[n] = dv;
        }
    }
}

// ---------------- final MLP + output assembly + counter reset ----------------
__global__ void k_final(int insel, const float* __restrict__ q,
                        const float* __restrict__ W1, const float* __restrict__ b1,
                        const float* __restrict__ W2, const float* __restrict__ b2,
                        float* __restrict__ out) {
    __shared__ float sW1[64 * 64];
    __shared__ float sW2[64];
    __shared__ float sb1[64];
    __shared__ float sq[32];
    int tid = threadIdx.x;
    int gtid = blockIdx.x * blockDim.x + tid;

    if (gtid < Nn) {
        g_deg[gtid] = 0.0f;
        g_indeg[gtid] = 0;
    }
    if (gtid == 0) { g_sum = 0.0f; g_tot = 0; }

    for (int i = tid; i < 4096; i += 256) sW1[i] = W1[i];
    if (tid < 64) { sW2[tid] = W2[tid]; sb1[tid] = b1[tid]; }
    if (tid < 32) sq[tid] = q[tid];
    __syncthreads();

    const float* __restrict__ hfin = hbuf(insel);
    int warp = gtid >> 5;
    int lane = tid & 31;
    if (warp >= Nn) return;
    int n = warp;
    float hv = hfin[n * Dd + lane];
    float a0 = sb1[lane], a1 = sb1[lane + 32];
    #pragma unroll
    for (int k = 0; k < 32; k++) {
        float xv = __shfl_sync(0xffffffffu, hv, k);
        a0 += xv * sW1[k * 64 + lane];
        a1 += xv * sW1[k * 64 + 32 + lane];
    }
    #pragma unroll
    for (int k = 0; k < 32; k++) {
        float xv = sq[k];
        a0 += xv * sW1[(32 + k) * 64 + lane];
        a1 += xv * sW1[(32 + k) * 64 + 32 + lane];
    }
    a0 = fmaxf(a0, 0.0f);
    a1 = fmaxf(a1, 0.0f);
    float p = a0 * sW2[lane] + a1 * sW2[lane + 32];
    #pragma unroll
    for (int o = 16; o; o >>= 1) p += __shfl_xor_sync(0xffffffffu, p, o);
    if (lane == 0) {
        out[n] = p + b2[0];
        out[Nn + n] = (float)g_pred[n];
    }
}

// ---------------- launch ----------------
extern "C" void kernel_launch(void* const* d_in, const int* in_sizes, int n_in,
                              void* d_out, int out_size) {
    const int*   node_in  = (const int*)d_in[0];
    const int*   node_out = (const int*)d_in[1];
    const float* ew       = (const float*)d_in[2];
    const int*   hptr     = (const int*)d_in[3];
    const float* qw       = (const float*)d_in[4];
    const float* relW     = (const float*)d_in[5];
    const float* relb     = (const float*)d_in[6];
    const float* linW     = (const float*)d_in[7];
    const float* linb     = (const float*)d_in[8];
    const float* W1       = (const float*)d_in[9];
    const float* b1       = (const float*)d_in[10];
    const float* W2       = (const float*)d_in[11];
    const float* b2       = (const float*)d_in[12];
    float* out = (float*)d_out;

    static bool attr_set = false;
    if (!attr_set) {
        cudaFuncSetAttribute(k_gemm<0>, cudaFuncAttributeMaxDynamicSharedMemorySize, GEMM_SMEM);
        cudaFuncSetAttribute(k_gemm<1>, cudaFuncAttributeMaxDynamicSharedMemorySize, GEMM_SMEM);
        attr_set = true;
    }

    k_init<<<(Ee + 255) / 256, 256>>>(hptr, qw, relW, relb, linW, node_out, ew);
    k_alloc<<<(Nn + 255) / 256, 256>>>();
    k_scatter<<<(Ee + 255) / 256, 256>>>(node_out, node_in, ew);

    int cur = 0;
    for (int l = 0; l < NL; l++) {
        if (l == 0)           k_agg0<<<(Nn + 7) / 8, 256>>>(hptr);
        else if (l == NL - 1) k_agg<1><<<(Nn + 7) / 8, 256>>>(hptr, cur, l);
        else                  k_agg<0><<<(Nn + 7) / 8, 256>>>(hptr, cur, l);
        if (l == NL - 2) k_gemm<1><<<(NR / BM), 256, GEMM_SMEM>>>(linb, l, cur ^ 1);
        else             k_gemm<0><<<(NR / BM), 256, GEMM_SMEM>>>(linb, l, cur ^ 1);
        cur ^= 1;
    }
    k_final<<<(Nn + 7) / 8, 256>>>(cur, qw, W1, b1, W2, b2, out);
}